// round 1
// baseline (speedup 1.0000x reference)
#include <cuda_runtime.h>
#include <math.h>

// ---------------------------------------------------------------------------
// Problem constants
// ---------------------------------------------------------------------------
constexpr int NU = 100000;
constexpr int NM = 20000;
constexpr int HD = 64;
constexpr int NE = 1000000;
constexpr int NEL = 500000;

// ---------------------------------------------------------------------------
// Device scratch (static __device__ arrays; no allocation allowed)
// ---------------------------------------------------------------------------
__device__ __align__(16) float g_xu0[NU * HD];        // layer-0 user features
__device__ __align__(16) float g_xm0[NM * HD];        // layer-0 movie features
__device__ __align__(16) float g_catu[NU * 3 * HD];   // JK concat (also holds layer outputs)
__device__ __align__(16) float g_catm[NM * 3 * HD];
__device__ __align__(16) float g_aggu[NU * HD];
__device__ __align__(16) float g_aggm[NM * HD];
__device__ __align__(16) float g_hu[NU * HD];
__device__ __align__(16) float g_hm[NM * HD];
__device__ __align__(16) float g_t1[(size_t)NEL * 64];
__device__ __align__(16) float g_t2[(size_t)NEL * 32];

__device__ int g_cntu[NU], g_cntm[NM];
__device__ int g_offu[NU + 1], g_offm[NM + 1];
__device__ int g_curu[NU], g_curm[NM];
__device__ int g_srcu[NE], g_srcm[NE];   // CSR neighbor (source-node) lists

__device__ float g_stats1[128], g_stats2[64];  // [sum | sumsq]
__device__ float g_ab1[128], g_ab2[64];        // [a | c] BN affine

// ---------------------------------------------------------------------------
// Init: gather x_u0 = user_emb[n_id], copy x_m0, zero counts + stats
// ---------------------------------------------------------------------------
__global__ void k_init(const int* __restrict__ n_id,
                       const float* __restrict__ user_emb,
                       const float* __restrict__ movie_x) {
  int t = blockIdx.x * blockDim.x + threadIdx.x;
  const int A = NU * 16, B = NM * 16, C = NU, D = NM;
  if (t < A) {
    int i = t >> 4, q = t & 15;
    ((float4*)g_xu0)[t] = ((const float4*)user_emb)[n_id[i] * 16 + q];
  } else if (t < A + B) {
    ((float4*)g_xm0)[t - A] = ((const float4*)movie_x)[t - A];
  } else if (t < A + B + C) {
    g_cntu[t - A - B] = 0;
  } else if (t < A + B + C + D) {
    g_cntm[t - A - B - C] = 0;
  } else {
    int j = t - (A + B + C + D);
    if (j < 128) g_stats1[j] = 0.f;
    else if (j < 192) g_stats2[j - 128] = 0.f;
  }
}

__global__ void k_count(const int* __restrict__ eu, const int* __restrict__ em) {
  int e = blockIdx.x * blockDim.x + threadIdx.x;
  if (e < NE) {
    atomicAdd(&g_cntu[eu[e]], 1);
    atomicAdd(&g_cntm[em[e]], 1);
  }
}

// Single-block exclusive scan (counting-sort offsets). n <= 100001.
__global__ void k_scan(const int* __restrict__ cnt, int n,
                       int* __restrict__ offs, int* __restrict__ cur) {
  __shared__ int sp[1024];
  int t = threadIdx.x;
  int C = (n + 1023) >> 10;
  int b = t * C;
  int e = min(b + C, n);
  int s = 0;
  for (int i = b; i < e; i++) s += cnt[i];
  sp[t] = s;
  __syncthreads();
  for (int d = 1; d < 1024; d <<= 1) {
    int v = (t >= d) ? sp[t - d] : 0;
    __syncthreads();
    sp[t] += v;
    __syncthreads();
  }
  int pre = (t == 0) ? 0 : sp[t - 1];
  for (int i = b; i < e; i++) {
    offs[i] = pre; cur[i] = pre; pre += cnt[i];
  }
  if (b < n && e == n) offs[n] = pre;
}

__global__ void k_fill(const int* __restrict__ eu, const int* __restrict__ em) {
  int e = blockIdx.x * blockDim.x + threadIdx.x;
  if (e < NE) {
    int u = eu[e], m = em[e];
    g_srcm[atomicAdd(&g_curm[m], 1)] = u;   // sources (users) feeding movie m
    g_srcu[atomicAdd(&g_curu[u], 1)] = m;   // sources (movies) feeding user u
  }
}

// ---------------------------------------------------------------------------
// Mean aggregation: warp per destination, lane owns 2 features.
// ---------------------------------------------------------------------------
__global__ void k_agg(const int* __restrict__ offs, const int* __restrict__ src,
                      const float* __restrict__ x, int ldx,
                      float* __restrict__ agg, int ndst) {
  int w = (blockIdx.x * blockDim.x + threadIdx.x) >> 5;
  int lane = threadIdx.x & 31;
  if (w >= ndst) return;
  int s0 = offs[w], s1 = offs[w + 1];
  float ax = 0.f, ay = 0.f;
  int s = s0;
  for (; s + 2 <= s1; s += 2) {
    int ga = src[s], gb = src[s + 1];
    float2 va = *(const float2*)(x + (size_t)ga * ldx + lane * 2);
    float2 vb = *(const float2*)(x + (size_t)gb * ldx + lane * 2);
    ax += va.x; ay += va.y;
    ax += vb.x; ay += vb.y;
  }
  if (s < s1) {
    int g = src[s];
    float2 v = *(const float2*)(x + (size_t)g * ldx + lane * 2);
    ax += v.x; ay += v.y;
  }
  float inv = 1.f / fmaxf((float)(s1 - s0), 1.f);
  *(float2*)(agg + (size_t)w * HD + lane * 2) = make_float2(ax * inv, ay * inv);
}

// ---------------------------------------------------------------------------
// Generic gathered-row GEMM: out[r][j] = act( sum_k A(r,k) * W(k,j) + bias[j] )
//   A row = [ src0[g0(r)] (K0 floats, opt. BN-affine+relu) | src1[g1(r)] (K1) ]
//   W     = [ W0 (K0 x NOUT) ; W1 (K1 x NOUT) ]  row-major
// Block: 64 rows x NOUT cols, 256 threads. Optional per-column stats (sum/sumsq).
// ---------------------------------------------------------------------------
template <int K0, int K1, int NOUT, int MODE0, int RELU, int STATS>
__global__ void k_gemm(const float* __restrict__ src0, int ld0, const int* __restrict__ gidx0,
                       const float* __restrict__ src1, int ld1, const int* __restrict__ gidx1,
                       const float* __restrict__ W0, const float* __restrict__ W1,
                       const float* __restrict__ bias, const float* __restrict__ aff,
                       float* __restrict__ out, int ldout, int nrows,
                       float* __restrict__ stats) {
  constexpr int K = K0 + K1;
  constexpr int K4 = K / 4;
  constexpr int TN = NOUT / 16;
  extern __shared__ float smem[];
  float* sA = smem;              // float4-layout: [k4][64 rows]
  float* sW = smem + 64 * K;     // [NOUT][K] (W transposed)
  int tid = threadIdx.x;
  int rowBase = blockIdx.x * 64;

  // Load W transposed into smem
  for (int v = tid; v < K * NOUT; v += 256) {
    int k = v / NOUT, j = v % NOUT;
    float w = (k < K0) ? W0[k * NOUT + j] : W1[(k - K0) * NOUT + j];
    sW[j * K + k] = w;
  }
  // Load A tile (gather + optional input transform)
  float4* sA4 = (float4*)sA;
  for (int v = tid; v < 16 * K; v += 256) {
    int r = v & 63, k4 = v >> 6;
    int k = k4 * 4;
    int row = rowBase + r;
    float4 val = make_float4(0.f, 0.f, 0.f, 0.f);
    if (row < nrows) {
      if (k < K0) {
        int g = gidx0 ? gidx0[row] : row;
        val = *(const float4*)(src0 + (size_t)g * ld0 + k);
        if constexpr (MODE0 == 1) {   // BN affine + relu on input
          val.x = fmaxf(aff[k] * val.x + aff[K0 + k], 0.f);
          val.y = fmaxf(aff[k + 1] * val.y + aff[K0 + k + 1], 0.f);
          val.z = fmaxf(aff[k + 2] * val.z + aff[K0 + k + 2], 0.f);
          val.w = fmaxf(aff[k + 3] * val.w + aff[K0 + k + 3], 0.f);
        }
      } else {
        int g = gidx1 ? gidx1[row] : row;
        val = *(const float4*)(src1 + (size_t)g * ld1 + (k - K0));
      }
    }
    sA4[v] = val;
  }
  __syncthreads();

  int lane = tid & 31;
  int tr = lane & 15;
  int tc = ((tid >> 5) << 1) | (lane >> 4);  // 0..15
  const float4* sW4 = (const float4*)sW;

  float acc[4][TN];
#pragma unroll
  for (int i = 0; i < 4; i++)
#pragma unroll
    for (int j = 0; j < TN; j++) acc[i][j] = 0.f;

#pragma unroll 4
  for (int k4 = 0; k4 < K4; k4++) {
    float4 a[4];
#pragma unroll
    for (int i = 0; i < 4; i++) a[i] = sA4[k4 * 64 + tr + i * 16];
#pragma unroll
    for (int j = 0; j < TN; j++) {
      float4 w = sW4[(tc * TN + j) * K4 + k4];
#pragma unroll
      for (int i = 0; i < 4; i++) {
        acc[i][j] += a[i].x * w.x;
        acc[i][j] += a[i].y * w.y;
        acc[i][j] += a[i].z * w.z;
        acc[i][j] += a[i].w * w.w;
      }
    }
  }

  float ssum[TN], ssq[TN];
  if constexpr (STATS) {
#pragma unroll
    for (int j = 0; j < TN; j++) { ssum[j] = 0.f; ssq[j] = 0.f; }
  }

#pragma unroll
  for (int i = 0; i < 4; i++) {
    int row = rowBase + tr + i * 16;
    if (row >= nrows) continue;
    float vals[TN];
#pragma unroll
    for (int j = 0; j < TN; j++) {
      int col = tc * TN + j;
      float v = acc[i][j] + bias[col];
      if constexpr (RELU) v = fmaxf(v, 0.f);
      vals[j] = v;
      if constexpr (STATS) { ssum[j] += v; ssq[j] += v * v; }
    }
    if constexpr (TN == 4) {
      *(float4*)(out + (size_t)row * ldout + tc * 4) =
          make_float4(vals[0], vals[1], vals[2], vals[3]);
    } else {
      *(float2*)(out + (size_t)row * ldout + tc * 2) =
          make_float2(vals[0], vals[1]);
    }
  }

  if constexpr (STATS) {
#pragma unroll
    for (int j = 0; j < TN; j++) {
      float s = ssum[j], q = ssq[j];
#pragma unroll
      for (int d = 8; d >= 1; d >>= 1) {
        s += __shfl_down_sync(0xffffffffu, s, d, 16);
        q += __shfl_down_sync(0xffffffffu, q, d, 16);
      }
      if (tr == 0) {
        int col = tc * TN + j;
        atomicAdd(&stats[col], s);          // compiles to RED (no return use)
        atomicAdd(&stats[NOUT + col], q);
      }
    }
  }
}

// BN training-mode affine: a = g*rsqrt(var+eps), c = be - mean*a
__global__ void k_bnprep(const float* __restrict__ stats, const float* __restrict__ g,
                         const float* __restrict__ be, float* __restrict__ ab,
                         int n, float invN) {
  int j = threadIdx.x;
  if (j < n) {
    float m = stats[j] * invN;
    float v = stats[n + j] * invN - m * m;
    float a = g[j] * rsqrtf(v + 1e-5f);
    ab[j] = a;
    ab[n + j] = be[j] - m * a;
  }
}

// Final: out[e] = sum_j relu(a2[j]*t2[e][j]+c2[j]) * W3[j] + b3
__global__ void k_final(const float* __restrict__ W3, const float* __restrict__ b3,
                        float* __restrict__ out) {
  __shared__ float sa[32], sc[32], sw[32];
  int tid = threadIdx.x;
  if (tid < 32) { sa[tid] = g_ab2[tid]; sc[tid] = g_ab2[32 + tid]; sw[tid] = W3[tid]; }
  __syncthreads();
  int e = blockIdx.x * blockDim.x + tid;
  if (e < NEL) {
    const float4* r = (const float4*)(g_t2 + (size_t)e * 32);
    float acc = b3[0];
#pragma unroll
    for (int q = 0; q < 8; q++) {
      float4 v = r[q];
      int k = q * 4;
      acc += fmaxf(sa[k] * v.x + sc[k], 0.f) * sw[k];
      acc += fmaxf(sa[k + 1] * v.y + sc[k + 1], 0.f) * sw[k + 1];
      acc += fmaxf(sa[k + 2] * v.z + sc[k + 2], 0.f) * sw[k + 2];
      acc += fmaxf(sa[k + 3] * v.w + sc[k + 3], 0.f) * sw[k + 3];
    }
    out[e] = acc;
  }
}

// ---------------------------------------------------------------------------
// Host launcher
// ---------------------------------------------------------------------------
static inline int cdiv(int a, int b) { return (a + b - 1) / b; }

extern "C" void kernel_launch(void* const* d_in, const int* in_sizes, int n_in,
                              void* d_out, int out_size) {
  const int*   n_id    = (const int*)d_in[0];
  const float* movie_x = (const float*)d_in[1];
  const int*   eu      = (const int*)d_in[2];
  const int*   em      = (const int*)d_in[3];
  const int*   lu      = (const int*)d_in[4];
  const int*   lm      = (const int*)d_in[5];
  const float* uemb    = (const float*)d_in[6];
  const float* Wl_um   = (const float*)d_in[7];
  const float* b_um    = (const float*)d_in[8];
  const float* Wr_um   = (const float*)d_in[9];
  const float* Wl_mu   = (const float*)d_in[10];
  const float* b_mu    = (const float*)d_in[11];
  const float* Wr_mu   = (const float*)d_in[12];
  const float* puW     = (const float*)d_in[13];
  const float* pub     = (const float*)d_in[14];
  const float* pmW     = (const float*)d_in[15];
  const float* pmb     = (const float*)d_in[16];
  const float* W1      = (const float*)d_in[17];
  const float* b1      = (const float*)d_in[18];
  const float* g1      = (const float*)d_in[19];
  const float* be1     = (const float*)d_in[20];
  const float* W2      = (const float*)d_in[21];
  const float* b2      = (const float*)d_in[22];
  const float* g2      = (const float*)d_in[23];
  const float* be2     = (const float*)d_in[24];
  const float* W3      = (const float*)d_in[25];
  const float* b3      = (const float*)d_in[26];
  float* out = (float*)d_out;

  // Resolve device-global addresses (not an allocation)
  float *xu0, *xm0, *catu, *catm, *aggu, *aggm, *hu, *hm, *t1, *t2;
  float *stats1, *stats2, *ab1, *ab2;
  int *cntu, *cntm, *offu, *offm, *curu, *curm, *srcu, *srcm;
  cudaGetSymbolAddress((void**)&xu0, g_xu0);
  cudaGetSymbolAddress((void**)&xm0, g_xm0);
  cudaGetSymbolAddress((void**)&catu, g_catu);
  cudaGetSymbolAddress((void**)&catm, g_catm);
  cudaGetSymbolAddress((void**)&aggu, g_aggu);
  cudaGetSymbolAddress((void**)&aggm, g_aggm);
  cudaGetSymbolAddress((void**)&hu, g_hu);
  cudaGetSymbolAddress((void**)&hm, g_hm);
  cudaGetSymbolAddress((void**)&t1, g_t1);
  cudaGetSymbolAddress((void**)&t2, g_t2);
  cudaGetSymbolAddress((void**)&stats1, g_stats1);
  cudaGetSymbolAddress((void**)&stats2, g_stats2);
  cudaGetSymbolAddress((void**)&ab1, g_ab1);
  cudaGetSymbolAddress((void**)&ab2, g_ab2);
  cudaGetSymbolAddress((void**)&cntu, g_cntu);
  cudaGetSymbolAddress((void**)&cntm, g_cntm);
  cudaGetSymbolAddress((void**)&offu, g_offu);
  cudaGetSymbolAddress((void**)&offm, g_offm);
  cudaGetSymbolAddress((void**)&curu, g_curu);
  cudaGetSymbolAddress((void**)&curm, g_curm);
  cudaGetSymbolAddress((void**)&srcu, g_srcu);
  cudaGetSymbolAddress((void**)&srcm, g_srcm);

  // Opt-in smem sizes (>48KB)
  cudaFuncSetAttribute((const void*)k_gemm<64, 64, 64, 0, 1, 0>,
                       cudaFuncAttributeMaxDynamicSharedMemorySize, 65536);
  cudaFuncSetAttribute((const void*)k_gemm<64, 64, 64, 0, 0, 1>,
                       cudaFuncAttributeMaxDynamicSharedMemorySize, 65536);
  cudaFuncSetAttribute((const void*)k_gemm<192, 0, 64, 0, 0, 0>,
                       cudaFuncAttributeMaxDynamicSharedMemorySize, 98304);

  // --- init + CSR build (once per call, derived from inputs) ---
  int initThreads = NU * 16 + NM * 16 + NU + NM + 192;
  k_init<<<cdiv(initThreads, 256), 256>>>(n_id, uemb, movie_x);
  k_count<<<cdiv(NE, 256), 256>>>(eu, em);
  k_scan<<<1, 1024>>>(cntu, NU, offu, curu);
  k_scan<<<1, 1024>>>(cntm, NM, offm, curm);
  k_fill<<<cdiv(NE, 256), 256>>>(eu, em);

  // --- 3 SAGE layers ---
  for (int l = 0; l < 3; l++) {
    const float* xu = l ? (catu + (l - 1) * 64) : xu0;
    const float* xm = l ? (catm + (l - 1) * 64) : xm0;
    int ldu = l ? 192 : 64;
    int ldm = l ? 192 : 64;

    k_agg<<<cdiv(NM * 32, 256), 256>>>(offm, srcm, xu, ldu, aggm, NM);
    k_agg<<<cdiv(NU * 32, 256), 256>>>(offu, srcu, xm, ldm, aggu, NU);

    // new_m = relu(aggm @ Wl_um[l] + b_um[l] + xm @ Wr_um[l])
    k_gemm<64, 64, 64, 0, 1, 0><<<cdiv(NM, 64), 256, 65536>>>(
        aggm, 64, nullptr, xm, ldm, nullptr,
        Wl_um + l * 4096, Wr_um + l * 4096, b_um + l * 64, nullptr,
        catm + l * 64, 192, NM, nullptr);
    // new_u = relu(aggu @ Wl_mu[l] + b_mu[l] + xu @ Wr_mu[l])
    k_gemm<64, 64, 64, 0, 1, 0><<<cdiv(NU, 64), 256, 65536>>>(
        aggu, 64, nullptr, xu, ldu, nullptr,
        Wl_mu + l * 4096, Wr_mu + l * 4096, b_mu + l * 64, nullptr,
        catu + l * 64, 192, NU, nullptr);
  }

  // --- JK-cat projections ---
  k_gemm<192, 0, 64, 0, 0, 0><<<cdiv(NU, 64), 256, 98304>>>(
      catu, 192, nullptr, nullptr, 0, nullptr,
      puW, nullptr, pub, nullptr, hu, 64, NU, nullptr);
  k_gemm<192, 0, 64, 0, 0, 0><<<cdiv(NM, 64), 256, 98304>>>(
      catm, 192, nullptr, nullptr, 0, nullptr,
      pmW, nullptr, pmb, nullptr, hm, 64, NM, nullptr);

  // --- classifier: t1 = [h_u[lu] | h_m[lm]] @ W1 + b1 (+ BN1 stats) ---
  k_gemm<64, 64, 64, 0, 0, 1><<<cdiv(NEL, 64), 256, 65536>>>(
      hu, 64, lu, hm, 64, lm,
      W1, W1 + 64 * 64, b1, nullptr, t1, 64, NEL, stats1);
  k_bnprep<<<1, 64>>>(stats1, g1, be1, ab1, 64, 1.f / NEL);

  // --- t2 = relu(bn1(t1)) @ W2 + b2 (+ BN2 stats) ---
  k_gemm<64, 0, 32, 1, 0, 1><<<cdiv(NEL, 64), 256, 24576>>>(
      t1, 64, nullptr, nullptr, 0, nullptr,
      W2, nullptr, b2, ab1, t2, 32, NEL, stats2);
  k_bnprep<<<1, 32>>>(stats2, g2, be2, ab2, 32, 1.f / NEL);

  // --- out = relu(bn2(t2)) @ W3 + b3 ---
  k_final<<<cdiv(NEL, 256), 256>>>(W3, b3, out);
}

// round 4
// speedup vs baseline: 1.1794x; 1.1794x over previous
#include <cuda_runtime.h>
#include <math.h>

// ---------------------------------------------------------------------------
// Problem constants
// ---------------------------------------------------------------------------
constexpr int NU = 100000;
constexpr int NM = 20000;
constexpr int HD = 64;
constexpr int NE = 1000000;
constexpr int NEL = 500000;

// ---------------------------------------------------------------------------
// Device scratch
// ---------------------------------------------------------------------------
__device__ __align__(16) float g_xu0[NU * HD];
__device__ __align__(16) float g_xm0[NM * HD];
__device__ __align__(16) float g_catu[NU * 3 * HD];
__device__ __align__(16) float g_catm[NM * 3 * HD];
__device__ __align__(16) float g_aggu[NU * HD];
__device__ __align__(16) float g_aggm[NM * HD];
__device__ __align__(16) float g_hu[NU * HD];
__device__ __align__(16) float g_hm[NM * HD];
__device__ __align__(16) float g_t1[(size_t)NEL * 64];
__device__ __align__(16) float g_t2[(size_t)NEL * 32];

__device__ int g_cntu[NU], g_cntm[NM];
__device__ int g_offu[NU + 1], g_offm[NM + 1];
__device__ int g_curu[NU], g_curm[NM];
__device__ int g_srcu[NE], g_srcm[NE];

__device__ float g_stats1[128], g_stats2[64];
__device__ float g_ab1[128], g_ab2[64];

// ---------------------------------------------------------------------------
// Packed-pair fp32 helpers. On Blackwell (__CUDA_ARCH__ >= 1000) these use the
// packed f32x2 FMA pipe; otherwise a bit-exact scalar two-FMA fallback.
// ---------------------------------------------------------------------------
struct fp2 { float lo, hi; };

__device__ __forceinline__ fp2 pk2(float lo, float hi) {
  fp2 r; r.lo = lo; r.hi = hi; return r;
}
__device__ __forceinline__ fp2 pkdup(float v) {
  fp2 r; r.lo = v; r.hi = v; return r;
}
__device__ __forceinline__ void ffma2(fp2& acc, fp2 a, fp2 b) {
#if defined(__CUDA_ARCH__) && (__CUDA_ARCH__ >= 1000)
  unsigned long long aa, bb, cc;
  asm("mov.b64 %0, {%1, %2};" : "=l"(aa) : "f"(a.lo), "f"(a.hi));
  asm("mov.b64 %0, {%1, %2};" : "=l"(bb) : "f"(b.lo), "f"(b.hi));
  asm("mov.b64 %0, {%1, %2};" : "=l"(cc) : "f"(acc.lo), "f"(acc.hi));
  asm("fma.rn.f32x2 %0, %1, %2, %0;" : "+l"(cc) : "l"(aa), "l"(bb));
  asm("mov.b64 {%0, %1}, %2;" : "=f"(acc.lo), "=f"(acc.hi) : "l"(cc));
#else
  acc.lo = fmaf(a.lo, b.lo, acc.lo);
  acc.hi = fmaf(a.hi, b.hi, acc.hi);
#endif
}

// ---------------------------------------------------------------------------
// Init: gather x_u0 = user_emb[n_id], copy x_m0, zero counts + stats
// ---------------------------------------------------------------------------
__global__ void k_init(const int* __restrict__ n_id,
                       const float* __restrict__ user_emb,
                       const float* __restrict__ movie_x) {
  int t = blockIdx.x * blockDim.x + threadIdx.x;
  const int A = NU * 16, B = NM * 16, C = NU, D = NM;
  if (t < A) {
    int i = t >> 4, q = t & 15;
    ((float4*)g_xu0)[t] = ((const float4*)user_emb)[n_id[i] * 16 + q];
  } else if (t < A + B) {
    ((float4*)g_xm0)[t - A] = ((const float4*)movie_x)[t - A];
  } else if (t < A + B + C) {
    g_cntu[t - A - B] = 0;
  } else if (t < A + B + C + D) {
    g_cntm[t - A - B - C] = 0;
  } else {
    int j = t - (A + B + C + D);
    if (j < 128) g_stats1[j] = 0.f;
    else if (j < 192) g_stats2[j - 128] = 0.f;
  }
}

__global__ void k_count(const int* __restrict__ eu, const int* __restrict__ em) {
  int e = blockIdx.x * blockDim.x + threadIdx.x;
  if (e < NE) {
    atomicAdd(&g_cntu[eu[e]], 1);
    atomicAdd(&g_cntm[em[e]], 1);
  }
}

// Both scans in one launch: block 0 = users, block 1 = movies.
__global__ void k_scan2() {
  __shared__ int sp[1024];
  const int* cnt; int n; int* offs; int* cur;
  if (blockIdx.x == 0) { cnt = g_cntu; n = NU; offs = g_offu; cur = g_curu; }
  else                 { cnt = g_cntm; n = NM; offs = g_offm; cur = g_curm; }
  int t = threadIdx.x;
  int C = (n + 1023) >> 10;
  int b = t * C;
  int e = min(b + C, n);
  int s = 0;
  for (int i = b; i < e; i++) s += cnt[i];
  sp[t] = s;
  __syncthreads();
  for (int d = 1; d < 1024; d <<= 1) {
    int v = (t >= d) ? sp[t - d] : 0;
    __syncthreads();
    sp[t] += v;
    __syncthreads();
  }
  int pre = (t == 0) ? 0 : sp[t - 1];
  for (int i = b; i < e; i++) {
    offs[i] = pre; cur[i] = pre; pre += cnt[i];
  }
  if (b < n && e == n) offs[n] = pre;
}

__global__ void k_fill(const int* __restrict__ eu, const int* __restrict__ em) {
  int e = blockIdx.x * blockDim.x + threadIdx.x;
  if (e < NE) {
    int u = eu[e], m = em[e];
    g_srcm[atomicAdd(&g_curm[m], 1)] = u;
    g_srcu[atomicAdd(&g_curu[u], 1)] = m;
  }
}

// ---------------------------------------------------------------------------
// Mean aggregation: warp per dst; two half-warps each take a neighbor,
// each of 16 lanes owns a float4 of features. shfl-combine at the end.
// ---------------------------------------------------------------------------
__global__ void k_agg(const int* __restrict__ offs, const int* __restrict__ src,
                      const float* __restrict__ x, int ldx,
                      float* __restrict__ agg, int ndst) {
  int w = (blockIdx.x * blockDim.x + threadIdx.x) >> 5;
  if (w >= ndst) return;
  int lane = threadIdx.x & 31;
  int half = lane >> 4, li = lane & 15;
  int s0 = offs[w], s1 = offs[w + 1];
  float ax = 0.f, ay = 0.f, az = 0.f, aw = 0.f;
  int s = s0 + half;
  for (; s + 2 < s1; s += 4) {
    int ga = __ldg(src + s);
    int gb = __ldg(src + s + 2);
    float4 va = *(const float4*)(x + (size_t)ga * ldx + li * 4);
    float4 vb = *(const float4*)(x + (size_t)gb * ldx + li * 4);
    ax += va.x; ay += va.y; az += va.z; aw += va.w;
    ax += vb.x; ay += vb.y; az += vb.z; aw += vb.w;
  }
  if (s < s1) {
    int g = __ldg(src + s);
    float4 v = *(const float4*)(x + (size_t)g * ldx + li * 4);
    ax += v.x; ay += v.y; az += v.z; aw += v.w;
  }
  ax += __shfl_xor_sync(0xffffffffu, ax, 16);
  ay += __shfl_xor_sync(0xffffffffu, ay, 16);
  az += __shfl_xor_sync(0xffffffffu, az, 16);
  aw += __shfl_xor_sync(0xffffffffu, aw, 16);
  if (half == 0) {
    float inv = 1.f / fmaxf((float)(s1 - s0), 1.f);
    *(float4*)(agg + (size_t)w * HD + li * 4) =
        make_float4(ax * inv, ay * inv, az * inv, aw * inv);
  }
}

// ---------------------------------------------------------------------------
// Gathered-row GEMM, 128-row x NOUT tile (64 rowpairs), 256 threads,
// packed-pair math.
//   A row = [ src0[g0(r)] (K0, opt. BN-affine+relu) | src1[g1(r)] (K1) ]
//   smem A layout: rowpair-packed fp2, stride S8=(K+2) pairs (16B pad).
// ---------------------------------------------------------------------------
template <int K0, int K1, int NOUT, int MODE0, int RELU, int STATS>
__global__ __launch_bounds__(256) void k_gemm(
    const float* __restrict__ src0, int ld0, const int* __restrict__ gidx0,
    const float* __restrict__ src1, int ld1, const int* __restrict__ gidx1,
    const float* __restrict__ W0, const float* __restrict__ W1,
    const float* __restrict__ bias, const float* __restrict__ aff,
    float* __restrict__ out, int ldout, int nrows,
    float* __restrict__ stats) {
  constexpr int K = K0 + K1;
  constexpr int K4 = K / 4;
  constexpr int TN = NOUT / 16;
  constexpr int S8 = K + 2;  // fp2 stride per rowpair (16B pad => bank rotate)
  extern __shared__ __align__(16) char smem_raw[];
  fp2* sA2 = (fp2*)smem_raw;                               // 64*S8 fp2
  float* sW = (float*)(smem_raw + 64 * (size_t)S8 * 8);    // [NOUT][K]
  int* sidx = (int*)(sW + NOUT * K);                       // 2*128 ints

  int tid = threadIdx.x;
  int rowBase = blockIdx.x * 128;

  // Preload gather indices (-1 => zero row)
  if (tid < 128) {
    int row = rowBase + tid;
    sidx[tid] = (row < nrows) ? (gidx0 ? gidx0[row] : row) : -1;
  } else if (K1 > 0) {
    int r = tid - 128;
    int row = rowBase + r;
    sidx[128 + r] = (row < nrows) ? (gidx1 ? gidx1[row] : row) : -1;
  }
  // W transposed into smem
  for (int v = tid; v < K * NOUT; v += 256) {
    int k = v / NOUT, j = v % NOUT;
    float w = (k < K0) ? W0[k * NOUT + j] : W1[(k - K0) * NOUT + j];
    sW[j * K + k] = w;
  }
  __syncthreads();

  // A tile: gather + pack 64 rowpairs x K4 float4-chunks
  for (int it = tid; it < 64 * K4; it += 256) {
    int rp = it & 63, k4 = it >> 6;
    int k = k4 * 4;
    float4 v0 = make_float4(0.f, 0.f, 0.f, 0.f);
    float4 v1 = make_float4(0.f, 0.f, 0.f, 0.f);
    if (k < K0) {
      int ga = sidx[2 * rp], gb = sidx[2 * rp + 1];
      if (ga >= 0) v0 = *(const float4*)(src0 + (size_t)ga * ld0 + k);
      if (gb >= 0) v1 = *(const float4*)(src0 + (size_t)gb * ld0 + k);
      if constexpr (MODE0 == 1) {  // BN affine + relu on input columns
        float a0 = aff[k], a1 = aff[k + 1], a2 = aff[k + 2], a3 = aff[k + 3];
        float c0 = aff[K0 + k], c1 = aff[K0 + k + 1], c2 = aff[K0 + k + 2], c3 = aff[K0 + k + 3];
        v0.x = fmaxf(a0 * v0.x + c0, 0.f); v0.y = fmaxf(a1 * v0.y + c1, 0.f);
        v0.z = fmaxf(a2 * v0.z + c2, 0.f); v0.w = fmaxf(a3 * v0.w + c3, 0.f);
        v1.x = fmaxf(a0 * v1.x + c0, 0.f); v1.y = fmaxf(a1 * v1.y + c1, 0.f);
        v1.z = fmaxf(a2 * v1.z + c2, 0.f); v1.w = fmaxf(a3 * v1.w + c3, 0.f);
      }
    } else {
      int ga = sidx[128 + 2 * rp], gb = sidx[128 + 2 * rp + 1];
      int kk = k - K0;
      if (ga >= 0) v0 = *(const float4*)(src1 + (size_t)ga * ld1 + kk);
      if (gb >= 0) v1 = *(const float4*)(src1 + (size_t)gb * ld1 + kk);
    }
    fp2* dst = sA2 + (size_t)rp * S8 + k;
    dst[0] = pk2(v0.x, v1.x);
    dst[1] = pk2(v0.y, v1.y);
    dst[2] = pk2(v0.z, v1.z);
    dst[3] = pk2(v0.w, v1.w);
  }
  __syncthreads();

  int lane = tid & 31;
  int tr = lane & 15;
  int tc = ((tid >> 5) << 1) | (lane >> 4);  // 0..15

  fp2 acc[4][TN];
#pragma unroll
  for (int r = 0; r < 4; r++)
#pragma unroll
    for (int j = 0; j < TN; j++) acc[r][j] = pk2(0.f, 0.f);

#pragma unroll 4
  for (int k4 = 0; k4 < K4; k4++) {
    int k = k4 * 4;
    fp2 a[4][4];
#pragma unroll
    for (int r = 0; r < 4; r++) {
      const float4* p = (const float4*)(sA2 + (size_t)(tr + r * 16) * S8 + k);
      float4 u = p[0];
      float4 v = p[1];
      a[r][0] = pk2(u.x, u.y); a[r][1] = pk2(u.z, u.w);
      a[r][2] = pk2(v.x, v.y); a[r][3] = pk2(v.z, v.w);
    }
#pragma unroll
    for (int j = 0; j < TN; j++) {
      float4 w4 = *(const float4*)(sW + (size_t)(tc * TN + j) * K + k);
      fp2 w0 = pkdup(w4.x), w1 = pkdup(w4.y);
      fp2 w2 = pkdup(w4.z), w3 = pkdup(w4.w);
#pragma unroll
      for (int r = 0; r < 4; r++) {
        ffma2(acc[r][j], a[r][0], w0);
        ffma2(acc[r][j], a[r][1], w1);
        ffma2(acc[r][j], a[r][2], w2);
        ffma2(acc[r][j], a[r][3], w3);
      }
    }
  }

  float ssum[TN], ssq[TN];
  if constexpr (STATS) {
#pragma unroll
    for (int j = 0; j < TN; j++) { ssum[j] = 0.f; ssq[j] = 0.f; }
  }

#pragma unroll
  for (int r = 0; r < 4; r++) {
    int rp = tr + r * 16;
    int row0 = rowBase + 2 * rp, row1 = row0 + 1;
    float v0[TN], v1[TN];
#pragma unroll
    for (int j = 0; j < TN; j++) {
      int col = tc * TN + j;
      float b = __ldg(bias + col);
      float lo = acc[r][j].lo + b;
      float hi = acc[r][j].hi + b;
      if constexpr (RELU) { lo = fmaxf(lo, 0.f); hi = fmaxf(hi, 0.f); }
      v0[j] = lo; v1[j] = hi;
      if constexpr (STATS) {
        if (row0 < nrows) { ssum[j] += lo; ssq[j] += lo * lo; }
        if (row1 < nrows) { ssum[j] += hi; ssq[j] += hi * hi; }
      }
    }
    if (row0 < nrows) {
      if constexpr (TN == 4)
        *(float4*)(out + (size_t)row0 * ldout + tc * 4) = make_float4(v0[0], v0[1], v0[2], v0[3]);
      else
        *(float2*)(out + (size_t)row0 * ldout + tc * 2) = make_float2(v0[0], v0[1]);
    }
    if (row1 < nrows) {
      if constexpr (TN == 4)
        *(float4*)(out + (size_t)row1 * ldout + tc * 4) = make_float4(v1[0], v1[1], v1[2], v1[3]);
      else
        *(float2*)(out + (size_t)row1 * ldout + tc * 2) = make_float2(v1[0], v1[1]);
    }
  }

  if constexpr (STATS) {
#pragma unroll
    for (int j = 0; j < TN; j++) {
      float s = ssum[j], q = ssq[j];
#pragma unroll
      for (int d = 8; d >= 1; d >>= 1) {
        s += __shfl_down_sync(0xffffffffu, s, d, 16);
        q += __shfl_down_sync(0xffffffffu, q, d, 16);
      }
      if (tr == 0) {
        int col = tc * TN + j;
        atomicAdd(&stats[col], s);
        atomicAdd(&stats[NOUT + col], q);
      }
    }
  }
}

// BN training-mode affine: a = g*rsqrt(var+eps), c = be - mean*a
__global__ void k_bnprep(const float* __restrict__ stats, const float* __restrict__ g,
                         const float* __restrict__ be, float* __restrict__ ab,
                         int n, float invN) {
  int j = threadIdx.x;
  if (j < n) {
    float m = stats[j] * invN;
    float v = stats[n + j] * invN - m * m;
    float a = g[j] * rsqrtf(v + 1e-5f);
    ab[j] = a;
    ab[n + j] = be[j] - m * a;
  }
}

// Final: out[e] = sum_j relu(a2[j]*t2[e][j]+c2[j]) * W3[j] + b3
__global__ void k_final(const float* __restrict__ W3, const float* __restrict__ b3,
                        float* __restrict__ out) {
  __shared__ float sa[32], sc[32], sw[32];
  int tid = threadIdx.x;
  if (tid < 32) { sa[tid] = g_ab2[tid]; sc[tid] = g_ab2[32 + tid]; sw[tid] = W3[tid]; }
  __syncthreads();
  int e = blockIdx.x * blockDim.x + tid;
  if (e < NEL) {
    const float4* r = (const float4*)(g_t2 + (size_t)e * 32);
    float acc = b3[0];
#pragma unroll
    for (int q = 0; q < 8; q++) {
      float4 v = r[q];
      int k = q * 4;
      acc += fmaxf(sa[k] * v.x + sc[k], 0.f) * sw[k];
      acc += fmaxf(sa[k + 1] * v.y + sc[k + 1], 0.f) * sw[k + 1];
      acc += fmaxf(sa[k + 2] * v.z + sc[k + 2], 0.f) * sw[k + 2];
      acc += fmaxf(sa[k + 3] * v.w + sc[k + 3], 0.f) * sw[k + 3];
    }
    out[e] = acc;
  }
}

// ---------------------------------------------------------------------------
// Host launcher
// ---------------------------------------------------------------------------
static inline int cdiv(int a, int b) { return (a + b - 1) / b; }
static inline int smemsz(int K, int NOUT) { return 64 * (K + 2) * 8 + NOUT * K * 4 + 1024; }

extern "C" void kernel_launch(void* const* d_in, const int* in_sizes, int n_in,
                              void* d_out, int out_size) {
  const int*   n_id    = (const int*)d_in[0];
  const float* movie_x = (const float*)d_in[1];
  const int*   eu      = (const int*)d_in[2];
  const int*   em      = (const int*)d_in[3];
  const int*   lu      = (const int*)d_in[4];
  const int*   lm      = (const int*)d_in[5];
  const float* uemb    = (const float*)d_in[6];
  const float* Wl_um   = (const float*)d_in[7];
  const float* b_um    = (const float*)d_in[8];
  const float* Wr_um   = (const float*)d_in[9];
  const float* Wl_mu   = (const float*)d_in[10];
  const float* b_mu    = (const float*)d_in[11];
  const float* Wr_mu   = (const float*)d_in[12];
  const float* puW     = (const float*)d_in[13];
  const float* pub     = (const float*)d_in[14];
  const float* pmW     = (const float*)d_in[15];
  const float* pmb     = (const float*)d_in[16];
  const float* W1      = (const float*)d_in[17];
  const float* b1      = (const float*)d_in[18];
  const float* g1      = (const float*)d_in[19];
  const float* be1     = (const float*)d_in[20];
  const float* W2      = (const float*)d_in[21];
  const float* b2      = (const float*)d_in[22];
  const float* g2      = (const float*)d_in[23];
  const float* be2     = (const float*)d_in[24];
  const float* W3      = (const float*)d_in[25];
  const float* b3      = (const float*)d_in[26];
  float* out = (float*)d_out;

  float *xu0, *xm0, *catu, *catm, *aggu, *aggm, *hu, *hm, *t1, *t2;
  float *stats1, *stats2, *ab1, *ab2;
  int *cntu, *cntm, *offu, *offm, *srcu, *srcm;
  cudaGetSymbolAddress((void**)&xu0, g_xu0);
  cudaGetSymbolAddress((void**)&xm0, g_xm0);
  cudaGetSymbolAddress((void**)&catu, g_catu);
  cudaGetSymbolAddress((void**)&catm, g_catm);
  cudaGetSymbolAddress((void**)&aggu, g_aggu);
  cudaGetSymbolAddress((void**)&aggm, g_aggm);
  cudaGetSymbolAddress((void**)&hu, g_hu);
  cudaGetSymbolAddress((void**)&hm, g_hm);
  cudaGetSymbolAddress((void**)&t1, g_t1);
  cudaGetSymbolAddress((void**)&t2, g_t2);
  cudaGetSymbolAddress((void**)&stats1, g_stats1);
  cudaGetSymbolAddress((void**)&stats2, g_stats2);
  cudaGetSymbolAddress((void**)&ab1, g_ab1);
  cudaGetSymbolAddress((void**)&ab2, g_ab2);
  cudaGetSymbolAddress((void**)&cntu, g_cntu);
  cudaGetSymbolAddress((void**)&cntm, g_cntm);
  cudaGetSymbolAddress((void**)&offu, g_offu);
  cudaGetSymbolAddress((void**)&offm, g_offm);
  cudaGetSymbolAddress((void**)&srcu, g_srcu);
  cudaGetSymbolAddress((void**)&srcm, g_srcm);

  const int SM128 = smemsz(128, 64);   // 100352 B: layer + classifier GEMM1
  const int SM192 = smemsz(192, 64);   // 149504 B: JK projections
  const int SM64  = smemsz(64, 32);    // 43008 B:  classifier GEMM2
  cudaFuncSetAttribute((const void*)k_gemm<64, 64, 64, 0, 1, 0>,
                       cudaFuncAttributeMaxDynamicSharedMemorySize, SM128);
  cudaFuncSetAttribute((const void*)k_gemm<64, 64, 64, 0, 0, 1>,
                       cudaFuncAttributeMaxDynamicSharedMemorySize, SM128);
  cudaFuncSetAttribute((const void*)k_gemm<192, 0, 64, 0, 0, 0>,
                       cudaFuncAttributeMaxDynamicSharedMemorySize, SM192);

  // --- init + CSR build ---
  int initThreads = NU * 16 + NM * 16 + NU + NM + 192;
  k_init<<<cdiv(initThreads, 256), 256>>>(n_id, uemb, movie_x);
  k_count<<<cdiv(NE, 256), 256>>>(eu, em);
  k_scan2<<<2, 1024>>>();
  k_fill<<<cdiv(NE, 256), 256>>>(eu, em);

  // --- 3 SAGE layers ---
  for (int l = 0; l < 3; l++) {
    const float* xu = l ? (catu + (l - 1) * 64) : xu0;
    const float* xm = l ? (catm + (l - 1) * 64) : xm0;
    int ldu = l ? 192 : 64;
    int ldm = l ? 192 : 64;

    k_agg<<<cdiv(NM * 32, 256), 256>>>(offm, srcm, xu, ldu, aggm, NM);
    k_agg<<<cdiv(NU * 32, 256), 256>>>(offu, srcu, xm, ldm, aggu, NU);

    k_gemm<64, 64, 64, 0, 1, 0><<<cdiv(NM, 128), 256, SM128>>>(
        aggm, 64, nullptr, xm, ldm, nullptr,
        Wl_um + l * 4096, Wr_um + l * 4096, b_um + l * 64, nullptr,
        catm + l * 64, 192, NM, nullptr);
    k_gemm<64, 64, 64, 0, 1, 0><<<cdiv(NU, 128), 256, SM128>>>(
        aggu, 64, nullptr, xu, ldu, nullptr,
        Wl_mu + l * 4096, Wr_mu + l * 4096, b_mu + l * 64, nullptr,
        catu + l * 64, 192, NU, nullptr);
  }

  // --- JK-cat projections ---
  k_gemm<192, 0, 64, 0, 0, 0><<<cdiv(NU, 128), 256, SM192>>>(
      catu, 192, nullptr, nullptr, 0, nullptr,
      puW, nullptr, pub, nullptr, hu, 64, NU, nullptr);
  k_gemm<192, 0, 64, 0, 0, 0><<<cdiv(NM, 128), 256, SM192>>>(
      catm, 192, nullptr, nullptr, 0, nullptr,
      pmW, nullptr, pmb, nullptr, hm, 64, NM, nullptr);

  // --- classifier: t1 = [h_u[lu] | h_m[lm]] @ W1 + b1 (+ BN1 stats) ---
  k_gemm<64, 64, 64, 0, 0, 1><<<cdiv(NEL, 128), 256, SM128>>>(
      hu, 64, lu, hm, 64, lm,
      W1, W1 + 64 * 64, b1, nullptr, t1, 64, NEL, stats1);
  k_bnprep<<<1, 64>>>(stats1, g1, be1, ab1, 64, 1.f / NEL);

  // --- t2 = relu(bn1(t1)) @ W2 + b2 (+ BN2 stats) ---
  k_gemm<64, 0, 32, 1, 0, 1><<<cdiv(NEL, 128), 256, SM64>>>(
      t1, 64, nullptr, nullptr, 0, nullptr,
      W2, nullptr, b2, ab1, t2, 32, NEL, stats2);
  k_bnprep<<<1, 32>>>(stats2, g2, be2, ab2, 32, 1.f / NEL);

  // --- out = relu(bn2(t2)) @ W3 + b3 ---
  k_final<<<cdiv(NEL, 256), 256>>>(W3, b3, out);
}